// round 1
// baseline (speedup 1.0000x reference)
#include <cuda_runtime.h>
#include <math.h>

// ---------------- scratch (device globals; allocation-free) ----------------
__device__ float g_h1[16 * 64 * 128 * 128];   // conv1 out
__device__ float g_h2[16 * 128 * 64 * 64];    // conv2 out / ping
__device__ float g_h3[16 * 128 * 64 * 64];    // conv3 out / pong
__device__ float g_t [16 * 32 * 64 * 64];     // residual bottleneck
__device__ float g_en[2048 * 4];              // normalized codebook

// ---------------- codebook normalization ----------------
__global__ void normalize_codebook_kernel(const float* __restrict__ cb) {
    int k = blockIdx.x * blockDim.x + threadIdx.x;
    if (k < 2048) {
        float x0 = cb[k * 4 + 0];
        float x1 = cb[k * 4 + 1];
        float x2 = cb[k * 4 + 2];
        float x3 = cb[k * 4 + 3];
        // match jnp.linalg.norm: sqrt(sum(x^2)); sequential adds, IEEE ops
        float ss = __fadd_rn(__fadd_rn(__fadd_rn(__fmul_rn(x0, x0), __fmul_rn(x1, x1)),
                                       __fmul_rn(x2, x2)), __fmul_rn(x3, x3));
        float den = sqrtf(ss) + 1e-12f;
        g_en[k * 4 + 0] = x0 / den;
        g_en[k * 4 + 1] = x1 / den;
        g_en[k * 4 + 2] = x2 / den;
        g_en[k * 4 + 3] = x3 / den;
    }
}

// ---------------- implicit-GEMM conv ----------------
// out[b][n][oy][ox] = sum_{cin,kh,kw} in[b][cin][oy*S-P+kh][ox*S-P+kw] * w[n][cin][kh][kw] + bias[n]
// GEMM view: M = B*HOUT*WOUT pixels, N = COUT, K = CIN*KH*KW.
template<int CIN, int COUT, int KH, int KW, int S, int P,
         int HIN, int WIN, int HOUT, int WOUT, int BN,
         bool RELU_IN, bool RELU_OUT, bool ADD>
__global__ __launch_bounds__(256)
void conv_gemm_kernel(const float* __restrict__ in,
                      const float* __restrict__ w,
                      const float* __restrict__ bias,
                      const float* __restrict__ res,
                      float* __restrict__ out) {
    constexpr int K  = CIN * KH * KW;
    constexpr int BM = 64;
    constexpr int BK = 16;
    constexpr int TN = BN / 16;   // 4 (BN=64) or 2 (BN=32)
    constexpr int KK = KH * KW;

    __shared__ float As[BK][BM];
    __shared__ float Bs[BK][BN];

    const int tid = threadIdx.x;
    const int tx  = tid & 15;
    const int ty  = tid >> 4;
    const int m0  = blockIdx.x * BM;
    const int n0  = blockIdx.y * BN;

    // Per-thread A-load coordinates (fixed across K tiles):
    // element e = tid + i*256 -> m_local = tid & 63, k_local = (tid>>6) + 4*i
    const int m_local = tid & 63;
    const int klc     = tid >> 6;          // 0..3
    {
        // nothing
    }
    const int m   = m0 + m_local;
    const int ox  = m % WOUT;
    const int oy  = (m / WOUT) % HOUT;
    const int b   = m / (WOUT * HOUT);
    const int iy0 = oy * S - P;
    const int ix0 = ox * S - P;
    const int ibase = b * CIN * HIN * WIN;

    float acc[4][TN];
#pragma unroll
    for (int i = 0; i < 4; i++)
#pragma unroll
        for (int j = 0; j < TN; j++) acc[i][j] = 0.0f;

    for (int k0 = 0; k0 < K; k0 += BK) {
        // ---- load A tile (implicit im2col gather) ----
#pragma unroll
        for (int i = 0; i < 4; i++) {
            const int kl  = klc + 4 * i;
            const int k   = k0 + kl;
            const int cin = k / KK;
            const int r   = k - cin * KK;
            const int kh  = r / KW;
            const int kw  = r - kh * KW;
            const int iy  = iy0 + kh;
            const int ix  = ix0 + kw;
            float v = 0.0f;
            if ((unsigned)iy < (unsigned)HIN && (unsigned)ix < (unsigned)WIN)
                v = in[ibase + cin * (HIN * WIN) + iy * WIN + ix];
            if (RELU_IN) v = fmaxf(v, 0.0f);
            As[kl][m_local] = v;
        }
        // ---- load B tile (weights are k-contiguous: coalesced float4) ----
        {
            constexpr int NB4 = BN * (BK / 4);   // number of float4 loads
            if (NB4 == 256 || tid < NB4) {
                const int nl = tid % BN;
                const int kg = tid / BN;         // 0..BK/4-1
                const float4 wv = *reinterpret_cast<const float4*>(
                    w + (size_t)(n0 + nl) * K + k0 + kg * 4);
                Bs[kg * 4 + 0][nl] = wv.x;
                Bs[kg * 4 + 1][nl] = wv.y;
                Bs[kg * 4 + 2][nl] = wv.z;
                Bs[kg * 4 + 3][nl] = wv.w;
            }
        }
        __syncthreads();

        // ---- compute ----
#pragma unroll
        for (int kk = 0; kk < BK; kk++) {
            const float4 av = *reinterpret_cast<const float4*>(&As[kk][ty * 4]);
            float a[4] = {av.x, av.y, av.z, av.w};
            float bv[TN];
            if (TN == 4) {
                const float4 b4 = *reinterpret_cast<const float4*>(&Bs[kk][tx * 4]);
                bv[0] = b4.x; bv[1] = b4.y; bv[2] = b4.z; bv[3] = b4.w;
            } else {
                const float2 b2 = *reinterpret_cast<const float2*>(&Bs[kk][tx * 2]);
                bv[0] = b2.x; bv[1] = b2.y;
            }
#pragma unroll
            for (int i = 0; i < 4; i++)
#pragma unroll
                for (int j = 0; j < TN; j++)
                    acc[i][j] = fmaf(a[i], bv[j], acc[i][j]);
        }
        __syncthreads();
    }

    // ---- epilogue ----
#pragma unroll
    for (int i = 0; i < 4; i++) {
        const int mm  = m0 + ty * 4 + i;
        const int oxx = mm % WOUT;
        const int oyy = (mm / WOUT) % HOUT;
        const int bb  = mm / (WOUT * HOUT);
#pragma unroll
        for (int j = 0; j < TN; j++) {
            const int n = n0 + tx * TN + j;
            float v = acc[i][j] + bias[n];
            const int oidx = ((bb * COUT + n) * HOUT + oyy) * WOUT + oxx;
            if (ADD) v += res[oidx];
            if (RELU_OUT) v = fmaxf(v, 0.0f);
            out[oidx] = v;
        }
    }
}

// ---------------- fused wpre (1x1, 128->4) + cosine VQ ----------------
// h: [16,128,64,64] (pre-relu); out: [16,4,64,64]
__global__ __launch_bounds__(256)
void vq_kernel(const float* __restrict__ h,
               const float* __restrict__ wpre,   // [4,128]
               const float* __restrict__ bpre,   // [4]
               const float* __restrict__ cb,     // [2048,4]
               float* __restrict__ out) {
    __shared__ float4 en_s[2048];
    __shared__ float  wp[128][4];
    __shared__ float  bp[4];

    const int tid = threadIdx.x;
    const float4* en4 = reinterpret_cast<const float4*>(g_en);
#pragma unroll
    for (int i = tid; i < 2048; i += 256) en_s[i] = en4[i];
    for (int i = tid; i < 512; i += 256) {
        const int d = i >> 7;
        const int c = i & 127;
        wp[c][d] = wpre[i];          // wpre[d*128 + c]
    }
    if (tid < 4) bp[tid] = bpre[tid];
    __syncthreads();

    const int pix = blockIdx.x * 256 + tid;
    const int b   = pix >> 12;         // / 4096
    const int yx  = pix & 4095;
    const float* hb = h + (size_t)b * 128 * 4096 + yx;

    float z0 = bp[0], z1 = bp[1], z2 = bp[2], z3 = bp[3];
#pragma unroll 8
    for (int c = 0; c < 128; c++) {
        const float v = fmaxf(hb[c * 4096], 0.0f);  // relu before wpre
        z0 = fmaf(wp[c][0], v, z0);
        z1 = fmaf(wp[c][1], v, z1);
        z2 = fmaf(wp[c][2], v, z2);
        z3 = fmaf(wp[c][3], v, z3);
    }

    // argmax over cosine sim; z-normalization is a positive scale -> argmax invariant
    float best = -INFINITY;
    int   bi   = 0;
#pragma unroll 4
    for (int k = 0; k < 2048; k++) {
        const float4 e = en_s[k];
        const float s = fmaf(z3, e.w, fmaf(z2, e.z, fmaf(z1, e.y, __fmul_rn(z0, e.x))));
        if (s > best) { best = s; bi = k; }  // strict > : first-index tie-break (jnp.argmax)
    }

    const float4 q = reinterpret_cast<const float4*>(cb)[bi];
    out[(b * 4 + 0) * 4096 + yx] = q.x;
    out[(b * 4 + 1) * 4096 + yx] = q.y;
    out[(b * 4 + 2) * 4096 + yx] = q.z;
    out[(b * 4 + 3) * 4096 + yx] = q.w;
}

// ---------------- launch ----------------
extern "C" void kernel_launch(void* const* d_in, const int* in_sizes, int n_in,
                              void* d_out, int out_size) {
    const float* cond = (const float*)d_in[0];
    const float* w1   = (const float*)d_in[1];
    const float* b1   = (const float*)d_in[2];
    const float* w2   = (const float*)d_in[3];
    const float* b2   = (const float*)d_in[4];
    const float* w3   = (const float*)d_in[5];
    const float* b3   = (const float*)d_in[6];
    const float* r1w1 = (const float*)d_in[7];
    const float* r1b1 = (const float*)d_in[8];
    const float* r1w2 = (const float*)d_in[9];
    const float* r1b2 = (const float*)d_in[10];
    const float* r2w1 = (const float*)d_in[11];
    const float* r2b1 = (const float*)d_in[12];
    const float* r2w2 = (const float*)d_in[13];
    const float* r2b2 = (const float*)d_in[14];
    const float* wpre = (const float*)d_in[15];
    const float* bpre = (const float*)d_in[16];
    const float* cb   = (const float*)d_in[17];
    float* out = (float*)d_out;

    float *h1, *h2, *h3, *t;
    cudaGetSymbolAddress((void**)&h1, g_h1);
    cudaGetSymbolAddress((void**)&h2, g_h2);
    cudaGetSymbolAddress((void**)&h3, g_h3);
    cudaGetSymbolAddress((void**)&t,  g_t);

    normalize_codebook_kernel<<<8, 256>>>(cb);

    // conv1: [16,1,256,256] -> relu -> [16,64,128,128]
    conv_gemm_kernel<1, 64, 4, 4, 2, 1, 256, 256, 128, 128, 64, false, true, false>
        <<<dim3(16 * 128 * 128 / 64, 1), 256>>>(cond, w1, b1, nullptr, h1);

    // conv2: -> relu -> [16,128,64,64]
    conv_gemm_kernel<64, 128, 4, 4, 2, 1, 128, 128, 64, 64, 64, false, true, false>
        <<<dim3(16 * 64 * 64 / 64, 2), 256>>>(h1, w2, b2, nullptr, h2);

    // conv3: -> [16,128,64,64] (no relu)
    conv_gemm_kernel<128, 128, 3, 3, 1, 1, 64, 64, 64, 64, 64, false, false, false>
        <<<dim3(16 * 64 * 64 / 64, 2), 256>>>(h2, w3, b3, nullptr, h3);

    // res block 1: t = conv3x3(relu(h3)); h2 = h3 + conv1x1(relu(t))
    conv_gemm_kernel<128, 32, 3, 3, 1, 1, 64, 64, 64, 64, 32, true, false, false>
        <<<dim3(16 * 64 * 64 / 64, 1), 256>>>(h3, r1w1, r1b1, nullptr, t);
    conv_gemm_kernel<32, 128, 1, 1, 1, 0, 64, 64, 64, 64, 64, true, false, true>
        <<<dim3(16 * 64 * 64 / 64, 2), 256>>>(t, r1w2, r1b2, h3, h2);

    // res block 2: t = conv3x3(relu(h2)); h3 = h2 + conv1x1(relu(t))
    conv_gemm_kernel<128, 32, 3, 3, 1, 1, 64, 64, 64, 64, 32, true, false, false>
        <<<dim3(16 * 64 * 64 / 64, 1), 256>>>(h2, r2w1, r2b1, nullptr, t);
    conv_gemm_kernel<32, 128, 1, 1, 1, 0, 64, 64, 64, 64, 64, true, false, true>
        <<<dim3(16 * 64 * 64 / 64, 2), 256>>>(t, r2w2, r2b2, h2, h3);

    // fused relu + wpre + VQ
    vq_kernel<<<16 * 64 * 64 / 256, 256>>>(h3, wpre, bpre, cb, out);
}

// round 2
// speedup vs baseline: 1.1603x; 1.1603x over previous
#include <cuda_runtime.h>
#include <math.h>

// ---------------- scratch (device globals; allocation-free) ----------------
__device__ float g_h1[16 * 64 * 128 * 128];   // conv1 out
__device__ float g_h2[16 * 128 * 64 * 64];    // conv2 out / ping
__device__ float g_h3[16 * 128 * 64 * 64];    // conv3 out / pong
__device__ float g_t [16 * 32 * 64 * 64];     // residual bottleneck
__device__ float g_en[2048 * 4];              // normalized codebook

// ---------------- f32x2 packed helpers (sm_103a) ----------------
__device__ __forceinline__ unsigned long long fma2(unsigned long long a,
                                                   unsigned long long b,
                                                   unsigned long long c) {
    unsigned long long d;
    asm("fma.rn.f32x2 %0, %1, %2, %3;" : "=l"(d) : "l"(a), "l"(b), "l"(c));
    return d;
}
__device__ __forceinline__ unsigned long long dup2(float x) {
    unsigned long long d;
    asm("mov.b64 %0, {%1, %1};" : "=l"(d) : "f"(x));
    return d;
}
__device__ __forceinline__ float2 unpack2(unsigned long long v) {
    float2 r;
    asm("mov.b64 {%0, %1}, %2;" : "=f"(r.x), "=f"(r.y) : "l"(v));
    return r;
}

// ---------------- codebook normalization ----------------
__global__ void normalize_codebook_kernel(const float* __restrict__ cb) {
    int k = blockIdx.x * blockDim.x + threadIdx.x;
    if (k < 2048) {
        float x0 = cb[k * 4 + 0];
        float x1 = cb[k * 4 + 1];
        float x2 = cb[k * 4 + 2];
        float x3 = cb[k * 4 + 3];
        float ss = __fadd_rn(__fadd_rn(__fadd_rn(__fmul_rn(x0, x0), __fmul_rn(x1, x1)),
                                       __fmul_rn(x2, x2)), __fmul_rn(x3, x3));
        float den = sqrtf(ss) + 1e-12f;
        g_en[k * 4 + 0] = x0 / den;
        g_en[k * 4 + 1] = x1 / den;
        g_en[k * 4 + 2] = x2 / den;
        g_en[k * 4 + 3] = x3 / den;
    }
}

// ---------------- implicit-GEMM conv, FFMA2 inner loop ----------------
// GEMM view: M = B*HOUT*WOUT pixels, N = COUT, K = CIN*KH*KW.
// BM=128, BK=8, 256 threads. Micro-tile: 8 M (as 4 f32x2 pairs) x TN N per thread.
template<int CIN, int COUT, int KH, int KW, int S, int P,
         int HIN, int WIN, int HOUT, int WOUT, int BN,
         bool RELU_IN, bool RELU_OUT, bool ADD>
__global__ __launch_bounds__(256)
void conv_gemm_kernel(const float* __restrict__ in,
                      const float* __restrict__ w,
                      const float* __restrict__ bias,
                      const float* __restrict__ res,
                      float* __restrict__ out) {
    constexpr int K   = CIN * KH * KW;
    constexpr int BM  = 128;
    constexpr int BK  = 8;
    constexpr int TN  = BN / 16;          // 8 / 4 / 2
    constexpr int KK  = KH * KW;
    constexpr int HW  = HOUT * WOUT;      // 4096 or 16384 (pow2)
    constexpr int LOG_HW = (HW == 16384) ? 14 : 12;
    static_assert(HW == (1 << LOG_HW), "HW must be pow2");
    constexpr int NB4 = BN * BK / 4;      // float4 weight loads per tile

    __shared__ __align__(16) float As[BK][BM];
    __shared__ __align__(16) float Bs[BK][BN];

    const int tid = threadIdx.x;
    const int tn  = tid & 15;             // N group
    const int tm  = tid >> 4;             // M group (0..15), 8 m each
    const int m0  = blockIdx.x * BM;
    const int n0  = blockIdx.y * BN;

    // A-gather coords: m_local fixed, k rows {klc, klc+2, klc+4, klc+6}
    const int m_local = tid & 127;
    const int klc     = tid >> 7;         // 0 or 1
    const int m   = m0 + m_local;
    const int ox  = m % WOUT;
    const int oy  = (m / WOUT) % HOUT;
    const int b   = m / (WOUT * HOUT);
    const int iy0 = oy * S - P;
    const int ix0 = ox * S - P;
    const int ibase = b * CIN * HIN * WIN;

    const bool wload = (NB4 == 256) || (tid < NB4);
    const int  nl    = tid % BN;
    const int  kg    = tid / BN;          // 0 or 1

    unsigned long long acc[4][TN];
#pragma unroll
    for (int ip = 0; ip < 4; ip++)
#pragma unroll
        for (int j = 0; j < TN; j++) acc[ip][j] = 0ull;

    // ---- prefetch first tile into registers ----
    float  a_stg[4];
    float4 w_stg = make_float4(0.f, 0.f, 0.f, 0.f);
    {
#pragma unroll
        for (int jj = 0; jj < 4; jj++) {
            const int k   = klc + 2 * jj;
            const int cin = k / KK;
            const int r   = k - cin * KK;
            const int kh  = r / KW;
            const int kw  = r - kh * KW;
            const int iy  = iy0 + kh;
            const int ix  = ix0 + kw;
            float v = 0.0f;
            if ((unsigned)iy < (unsigned)HIN && (unsigned)ix < (unsigned)WIN)
                v = in[ibase + cin * (HIN * WIN) + iy * WIN + ix];
            if (RELU_IN) v = fmaxf(v, 0.0f);
            a_stg[jj] = v;
        }
        if (wload)
            w_stg = *reinterpret_cast<const float4*>(w + (size_t)(n0 + nl) * K + kg * 4);
    }

    for (int k0 = 0; k0 < K; k0 += BK) {
        // ---- commit staged tile to smem ----
#pragma unroll
        for (int jj = 0; jj < 4; jj++)
            As[klc + 2 * jj][m_local] = a_stg[jj];
        if (wload) {
            Bs[kg * 4 + 0][nl] = w_stg.x;
            Bs[kg * 4 + 1][nl] = w_stg.y;
            Bs[kg * 4 + 2][nl] = w_stg.z;
            Bs[kg * 4 + 3][nl] = w_stg.w;
        }
        __syncthreads();

        // ---- prefetch next tile (overlaps with compute below) ----
        const int kn0 = k0 + BK;
        if (kn0 < K) {
#pragma unroll
            for (int jj = 0; jj < 4; jj++) {
                const int k   = kn0 + klc + 2 * jj;
                const int cin = k / KK;
                const int r   = k - cin * KK;
                const int kh  = r / KW;
                const int kw  = r - kh * KW;
                const int iy  = iy0 + kh;
                const int ix  = ix0 + kw;
                float v = 0.0f;
                if ((unsigned)iy < (unsigned)HIN && (unsigned)ix < (unsigned)WIN)
                    v = in[ibase + cin * (HIN * WIN) + iy * WIN + ix];
                if (RELU_IN) v = fmaxf(v, 0.0f);
                a_stg[jj] = v;
            }
            if (wload)
                w_stg = *reinterpret_cast<const float4*>(
                    w + (size_t)(n0 + nl) * K + kn0 + kg * 4);
        }

        // ---- compute: 8 kk x (4 m-pairs x TN) FFMA2 ----
#pragma unroll
        for (int kk = 0; kk < BK; kk++) {
            const ulonglong2 a01 = *reinterpret_cast<const ulonglong2*>(&As[kk][tm * 8]);
            const ulonglong2 a23 = *reinterpret_cast<const ulonglong2*>(&As[kk][tm * 8 + 4]);
            unsigned long long ap[4] = {a01.x, a01.y, a23.x, a23.y};

            unsigned long long bd[TN];
            if (TN == 8) {
                const float4 b0 = *reinterpret_cast<const float4*>(&Bs[kk][tn * 8]);
                const float4 b1 = *reinterpret_cast<const float4*>(&Bs[kk][tn * 8 + 4]);
                bd[0] = dup2(b0.x); bd[1] = dup2(b0.y); bd[2] = dup2(b0.z); bd[3] = dup2(b0.w);
                bd[4] = dup2(b1.x); bd[5] = dup2(b1.y); bd[6] = dup2(b1.z); bd[7] = dup2(b1.w);
            } else if (TN == 4) {
                const float4 b0 = *reinterpret_cast<const float4*>(&Bs[kk][tn * 4]);
                bd[0] = dup2(b0.x); bd[1] = dup2(b0.y); bd[2] = dup2(b0.z); bd[3] = dup2(b0.w);
            } else {
                const float2 b0 = *reinterpret_cast<const float2*>(&Bs[kk][tn * 2]);
                bd[0] = dup2(b0.x); bd[1] = dup2(b0.y);
            }
#pragma unroll
            for (int ip = 0; ip < 4; ip++)
#pragma unroll
                for (int j = 0; j < TN; j++)
                    acc[ip][j] = fma2(ap[ip], bd[j], acc[ip][j]);
        }
        __syncthreads();
    }

    // ---- epilogue: 8 contiguous m per (thread, n) -> two STG.128 ----
    const int m_start = m0 + tm * 8;
    const int bb  = m_start >> LOG_HW;
    const int yx  = m_start & (HW - 1);
#pragma unroll
    for (int j = 0; j < TN; j++) {
        const int n = n0 + tn * TN + j;
        const float bv = bias[n];
        const size_t obase = (((size_t)(bb * COUT + n)) << LOG_HW) + yx;
        float v[8];
#pragma unroll
        for (int ip = 0; ip < 4; ip++) {
            const float2 p = unpack2(acc[ip][j]);
            v[2 * ip]     = p.x + bv;
            v[2 * ip + 1] = p.y + bv;
        }
        if (ADD) {
            const float4 r0 = *reinterpret_cast<const float4*>(res + obase);
            const float4 r1 = *reinterpret_cast<const float4*>(res + obase + 4);
            v[0] += r0.x; v[1] += r0.y; v[2] += r0.z; v[3] += r0.w;
            v[4] += r1.x; v[5] += r1.y; v[6] += r1.z; v[7] += r1.w;
        }
        if (RELU_OUT) {
#pragma unroll
            for (int i = 0; i < 8; i++) v[i] = fmaxf(v[i], 0.0f);
        }
        *reinterpret_cast<float4*>(out + obase)     = make_float4(v[0], v[1], v[2], v[3]);
        *reinterpret_cast<float4*>(out + obase + 4) = make_float4(v[4], v[5], v[6], v[7]);
    }
}

// ---------------- fused wpre (1x1, 128->4) + cosine VQ ----------------
__global__ __launch_bounds__(256)
void vq_kernel(const float* __restrict__ h,
               const float* __restrict__ wpre,   // [4,128]
               const float* __restrict__ bpre,   // [4]
               const float* __restrict__ cb,     // [2048,4]
               float* __restrict__ out) {
    __shared__ float4 en_s[2048];
    __shared__ float  wp[128][4];
    __shared__ float  bp[4];

    const int tid = threadIdx.x;
    const float4* en4 = reinterpret_cast<const float4*>(g_en);
#pragma unroll
    for (int i = tid; i < 2048; i += 256) en_s[i] = en4[i];
    for (int i = tid; i < 512; i += 256) {
        const int d = i >> 7;
        const int c = i & 127;
        wp[c][d] = wpre[i];
    }
    if (tid < 4) bp[tid] = bpre[tid];
    __syncthreads();

    const int pix = blockIdx.x * 256 + tid;
    const int b   = pix >> 12;
    const int yx  = pix & 4095;
    const float* hb = h + (size_t)b * 128 * 4096 + yx;

    float z0 = bp[0], z1 = bp[1], z2 = bp[2], z3 = bp[3];
#pragma unroll 8
    for (int c = 0; c < 128; c++) {
        const float v = fmaxf(hb[c * 4096], 0.0f);
        z0 = fmaf(wp[c][0], v, z0);
        z1 = fmaf(wp[c][1], v, z1);
        z2 = fmaf(wp[c][2], v, z2);
        z3 = fmaf(wp[c][3], v, z3);
    }

    float best = -INFINITY;
    int   bi   = 0;
#pragma unroll 4
    for (int k = 0; k < 2048; k++) {
        const float4 e = en_s[k];
        const float s = fmaf(z3, e.w, fmaf(z2, e.z, fmaf(z1, e.y, __fmul_rn(z0, e.x))));
        if (s > best) { best = s; bi = k; }   // strict > : first-index tie-break
    }

    const float4 q = reinterpret_cast<const float4*>(cb)[bi];
    out[(b * 4 + 0) * 4096 + yx] = q.x;
    out[(b * 4 + 1) * 4096 + yx] = q.y;
    out[(b * 4 + 2) * 4096 + yx] = q.z;
    out[(b * 4 + 3) * 4096 + yx] = q.w;
}

// ---------------- launch ----------------
extern "C" void kernel_launch(void* const* d_in, const int* in_sizes, int n_in,
                              void* d_out, int out_size) {
    const float* cond = (const float*)d_in[0];
    const float* w1   = (const float*)d_in[1];
    const float* b1   = (const float*)d_in[2];
    const float* w2   = (const float*)d_in[3];
    const float* b2   = (const float*)d_in[4];
    const float* w3   = (const float*)d_in[5];
    const float* b3   = (const float*)d_in[6];
    const float* r1w1 = (const float*)d_in[7];
    const float* r1b1 = (const float*)d_in[8];
    const float* r1w2 = (const float*)d_in[9];
    const float* r1b2 = (const float*)d_in[10];
    const float* r2w1 = (const float*)d_in[11];
    const float* r2b1 = (const float*)d_in[12];
    const float* r2w2 = (const float*)d_in[13];
    const float* r2b2 = (const float*)d_in[14];
    const float* wpre = (const float*)d_in[15];
    const float* bpre = (const float*)d_in[16];
    const float* cb   = (const float*)d_in[17];
    float* out = (float*)d_out;

    float *h1, *h2, *h3, *t;
    cudaGetSymbolAddress((void**)&h1, g_h1);
    cudaGetSymbolAddress((void**)&h2, g_h2);
    cudaGetSymbolAddress((void**)&h3, g_h3);
    cudaGetSymbolAddress((void**)&t,  g_t);

    normalize_codebook_kernel<<<8, 256>>>(cb);

    // conv1: [16,1,256,256] -> relu -> [16,64,128,128]
    conv_gemm_kernel<1, 64, 4, 4, 2, 1, 256, 256, 128, 128, 64, false, true, false>
        <<<dim3(16 * 128 * 128 / 128, 1), 256>>>(cond, w1, b1, nullptr, h1);

    // conv2: -> relu -> [16,128,64,64]
    conv_gemm_kernel<64, 128, 4, 4, 2, 1, 128, 128, 64, 64, 128, false, true, false>
        <<<dim3(16 * 64 * 64 / 128, 1), 256>>>(h1, w2, b2, nullptr, h2);

    // conv3: -> [16,128,64,64] (no relu)
    conv_gemm_kernel<128, 128, 3, 3, 1, 1, 64, 64, 64, 64, 128, false, false, false>
        <<<dim3(16 * 64 * 64 / 128, 1), 256>>>(h2, w3, b3, nullptr, h3);

    // res block 1
    conv_gemm_kernel<128, 32, 3, 3, 1, 1, 64, 64, 64, 64, 32, true, false, false>
        <<<dim3(16 * 64 * 64 / 128, 1), 256>>>(h3, r1w1, r1b1, nullptr, t);
    conv_gemm_kernel<32, 128, 1, 1, 1, 0, 64, 64, 64, 64, 128, true, false, true>
        <<<dim3(16 * 64 * 64 / 128, 1), 256>>>(t, r1w2, r1b2, h3, h2);

    // res block 2
    conv_gemm_kernel<128, 32, 3, 3, 1, 1, 64, 64, 64, 64, 32, true, false, false>
        <<<dim3(16 * 64 * 64 / 128, 1), 256>>>(h2, r2w1, r2b1, nullptr, t);
    conv_gemm_kernel<32, 128, 1, 1, 1, 0, 64, 64, 64, 64, 128, true, false, true>
        <<<dim3(16 * 64 * 64 / 128, 1), 256>>>(t, r2w2, r2b2, h2, h3);

    // fused relu + wpre + VQ
    vq_kernel<<<16 * 64 * 64 / 256, 256>>>(h3, wpre, bpre, cb, out);
}